// round 12
// baseline (speedup 1.0000x reference)
#include <cuda_runtime.h>

// ---------------------------------------------------------------------------
// FCOS decoder head, fp32 SIMT implicit-GEMM implementation, packed-f32x2 core.
//   5 FPN levels (128^2 .. 8^2), batch 4, C=256.
//   Each head: 4 x [conv3x3 -> BN(scale,bias) -> ReLU] -> 1x1 conv (+bias).
//   cls head: 80 ch out. reg head: 5 ch out -> ch0 = centerness,
//   ch1..4 = max(raw * stride, 0).
// Inner loops use fma.rn.f32x2 (FFMA2) — 2 fp32 FMAs per instruction, the only
// way to reach the full 256 FLOP/cyc/SM fp32 rate on sm_103a (ptxas never
// emits it from C++). Accumulators are paired over adjacent output channels;
// weight pairs come straight out of SMEM as 64-bit register pairs.
// ---------------------------------------------------------------------------

#define FPN_LEVELS 5
#define CH 256

typedef unsigned long long u64;

__device__ __forceinline__ void ffma2(u64& d, u64 a, u64 b) {
    asm("fma.rn.f32x2 %0, %1, %2, %0;" : "+l"(d) : "l"(a), "l"(b));
}
__device__ __forceinline__ u64 pack2(float x) {
    unsigned xi = __float_as_uint(x);
    u64 r;
    asm("mov.b64 %0, {%1, %1};" : "=l"(r) : "r"(xi));
    return r;
}
__device__ __forceinline__ float lane(u64 v, int h) {
    float2 f = *reinterpret_cast<const float2*>(&v);
    return h ? f.y : f.x;
}

// Scratch (device globals: allocation-free, graph-capturable).
__device__ float g_bufA[4 * 256 * 128 * 128];   // 64 MB ping
__device__ float g_bufB[4 * 256 * 128 * 128];   // 64 MB pong
__device__ float g_wt[2 * 4 * 2304 * 256];      // folded weights, 18 MB
                                                // layout: [head][layer][(c*9+t)][k]

// ---------------------------------------------------------------------------
// Fold BN scale into 3x3 weights + transpose to [(c*9+t)][k].
// total elements = 2 heads * 4 layers * 256c * 9t * 256k = 4,718,592
// ---------------------------------------------------------------------------
__global__ void fold_weights_kernel(const float* __restrict__ cls_w,
                                    const float* __restrict__ cls_s,
                                    const float* __restrict__ reg_w,
                                    const float* __restrict__ reg_s) {
    int o = blockIdx.x * 256 + threadIdx.x;     // exact grid, no guard needed
    int k    = o & 255;
    int rest = o >> 8;                          // ((head*4+L)*256 + c)*9 + t
    int t    = rest % 9;
    int q    = rest / 9;                        // (head*4+L)*256 + c
    int c    = q & 255;
    int q2   = q >> 8;                          // head*4 + L
    int L    = q2 & 3;
    int head = q2 >> 2;
    const float* w = head ? reg_w : cls_w;
    const float* s = head ? reg_s : cls_s;
    // source layout: [L][k][c][3][3]
    g_wt[o] = w[((L * 256 + k) * 256 + c) * 9 + t] * s[L * 256 + k];
}

// ---------------------------------------------------------------------------
// Big conv3x3: CTA tile = 128 out-ch x (8 rows x 16 cols) spatial.
// 256 threads: 16 k-threads (8 ch each) x 16 spatial threads (1 row x 8 cols).
// Per-thread tile: 8 spatial x 8 out-ch, held as 8x4 f32x2 pairs.
// Used for levels 0,1 (H,W multiples of 16/8 -> no output guards needed).
// ---------------------------------------------------------------------------
__global__ __launch_bounds__(256, 2)
void conv3x3_big(const float* __restrict__ in, float* __restrict__ out,
                 const float* __restrict__ wt,      // layer base: [(c*9+t)*256 + k]
                 const float* __restrict__ bias,    // 256
                 int H, int W) {
    __shared__ __align__(16) float in_s[8 * 10 * 20];   // 8c x 10y x 18x (pad 20)
    __shared__ __align__(16) float w_s[72 * 128];       // [(cc*9+t)][k]

    const int tid = threadIdx.x;
    const int st  = tid & 15;
    const int kt  = tid >> 4;            // 0..15, 8 out-ch each
    const int r   = st & 7;              // output row within tile
    const int c2  = st >> 3;             // 0/1 -> x offset 0 or 8
    const int x0  = blockIdx.x * 16;
    const int y0  = blockIdx.y * 8;
    const int n   = blockIdx.z >> 1;
    const int k0  = (blockIdx.z & 1) * 128;
    const float* inb = in + ((size_t)n * CH) * H * W;

    u64 acc[8][4];                        // [spatial xi][k-pair]
#pragma unroll
    for (int a = 0; a < 8; ++a)
#pragma unroll
        for (int b = 0; b < 4; ++b) acc[a][b] = 0ull;

    for (int c0 = 0; c0 < CH; c0 += 8) {
        // stage input patch 8c x 10y x 18x (with halo + zero padding)
        for (int i = tid; i < 1440; i += 256) {
            int x  = i % 18;
            int yq = i / 18;
            int y  = yq % 10;
            int cc = yq / 10;
            int iy = y0 - 1 + y;
            int ix = x0 - 1 + x;
            float v = 0.f;
            if ((unsigned)iy < (unsigned)H && (unsigned)ix < (unsigned)W)
                v = inb[((c0 + cc) * H + iy) * W + ix];
            in_s[cc * 200 + y * 20 + x] = v;
        }
        // stage weights 8c x 9t x 128k  (coalesced LDG, conflict-free STS)
        {
            const float* wp = wt + (size_t)(c0 * 9) * 256 + k0;
            for (int j = tid; j < 9216; j += 256) {
                int k = j & 127;
                int q = j >> 7;          // cc*9 + t
                w_s[j] = wp[q * 256 + k];
            }
        }
        __syncthreads();

#pragma unroll 2
        for (int cc = 0; cc < 8; ++cc) {
#pragma unroll
            for (int dy = 0; dy < 3; ++dy) {
                const float* rowp = &in_s[cc * 200 + (r + dy) * 20 + c2 * 8];
                float4 a0 = *(const float4*)rowp;
                float4 a1 = *(const float4*)(rowp + 4);
                u64 rp[10];
                rp[0] = pack2(a0.x); rp[1] = pack2(a0.y);
                rp[2] = pack2(a0.z); rp[3] = pack2(a0.w);
                rp[4] = pack2(a1.x); rp[5] = pack2(a1.y);
                rp[6] = pack2(a1.z); rp[7] = pack2(a1.w);
                rp[8] = pack2(rowp[8]); rp[9] = pack2(rowp[9]);
                const float* wrow = &w_s[(cc * 9 + dy * 3) * 128 + kt * 8];
#pragma unroll
                for (int dx = 0; dx < 3; ++dx) {
                    ulonglong2 wv0 = *(const ulonglong2*)(wrow + dx * 128);
                    ulonglong2 wv1 = *(const ulonglong2*)(wrow + dx * 128 + 4);
                    const u64 w0 = wv0.x, w1 = wv0.y, w2 = wv1.x, w3 = wv1.y;
#pragma unroll
                    for (int xi = 0; xi < 8; ++xi) {
                        u64 xv = rp[xi + dx];
                        ffma2(acc[xi][0], xv, w0);
                        ffma2(acc[xi][1], xv, w1);
                        ffma2(acc[xi][2], xv, w2);
                        ffma2(acc[xi][3], xv, w3);
                    }
                }
            }
        }
        __syncthreads();
    }

    const int gy  = y0 + r;
    const int gxb = x0 + c2 * 8;
#pragma unroll
    for (int kp = 0; kp < 4; ++kp) {
#pragma unroll
        for (int h = 0; h < 2; ++h) {
            int k = k0 + kt * 8 + kp * 2 + h;
            float bv = bias[k];
            float4 o0, o1;
            o0.x = fmaxf(lane(acc[0][kp], h) + bv, 0.f);
            o0.y = fmaxf(lane(acc[1][kp], h) + bv, 0.f);
            o0.z = fmaxf(lane(acc[2][kp], h) + bv, 0.f);
            o0.w = fmaxf(lane(acc[3][kp], h) + bv, 0.f);
            o1.x = fmaxf(lane(acc[4][kp], h) + bv, 0.f);
            o1.y = fmaxf(lane(acc[5][kp], h) + bv, 0.f);
            o1.z = fmaxf(lane(acc[6][kp], h) + bv, 0.f);
            o1.w = fmaxf(lane(acc[7][kp], h) + bv, 0.f);
            float* op = out + ((size_t)(n * CH + k) * H + gy) * W + gxb;
            *(float4*)op       = o0;
            *(float4*)(op + 4) = o1;
        }
    }
}

// ---------------------------------------------------------------------------
// Small conv3x3: CTA tile = 64 out-ch x (8x8) spatial, 4 spatial x 2 k-pairs.
// Used for levels 2..4 (H,W multiples of 8) to keep grids >= 16 CTAs.
// ---------------------------------------------------------------------------
__global__ __launch_bounds__(256, 2)
void conv3x3_small(const float* __restrict__ in, float* __restrict__ out,
                   const float* __restrict__ wt,
                   const float* __restrict__ bias,
                   int H, int W) {
    __shared__ __align__(16) float in_s[8 * 10 * 12];   // 8c x 10y x 10x (pad 12)
    __shared__ __align__(16) float w_s[72 * 64];

    const int tid = threadIdx.x;
    const int st  = tid & 15;
    const int kt  = tid >> 4;            // 0..15, 4 out-ch each
    const int r   = st & 7;
    const int c2  = st >> 3;             // x offset 0 or 4
    const int x0  = blockIdx.x * 8;
    const int y0  = blockIdx.y * 8;
    const int n   = blockIdx.z >> 2;
    const int k0  = (blockIdx.z & 3) * 64;
    const float* inb = in + ((size_t)n * CH) * H * W;

    u64 acc[4][2];
#pragma unroll
    for (int a = 0; a < 4; ++a)
#pragma unroll
        for (int b = 0; b < 2; ++b) acc[a][b] = 0ull;

    for (int c0 = 0; c0 < CH; c0 += 8) {
        for (int i = tid; i < 800; i += 256) {
            int x  = i % 10;
            int yq = i / 10;
            int y  = yq % 10;
            int cc = yq / 10;
            int iy = y0 - 1 + y;
            int ix = x0 - 1 + x;
            float v = 0.f;
            if ((unsigned)iy < (unsigned)H && (unsigned)ix < (unsigned)W)
                v = inb[((c0 + cc) * H + iy) * W + ix];
            in_s[cc * 120 + y * 12 + x] = v;
        }
        {
            const float* wp = wt + (size_t)(c0 * 9) * 256 + k0;
            for (int j = tid; j < 4608; j += 256) {
                int k = j & 63;
                int q = j >> 6;
                w_s[j] = wp[q * 256 + k];
            }
        }
        __syncthreads();

#pragma unroll
        for (int cc = 0; cc < 8; ++cc) {
#pragma unroll
            for (int dy = 0; dy < 3; ++dy) {
                const float* rowp = &in_s[cc * 120 + (r + dy) * 12 + c2 * 4];
                float4 a0 = *(const float4*)rowp;
                u64 rp[6];
                rp[0] = pack2(a0.x); rp[1] = pack2(a0.y);
                rp[2] = pack2(a0.z); rp[3] = pack2(a0.w);
                rp[4] = pack2(rowp[4]); rp[5] = pack2(rowp[5]);
                const float* wrow = &w_s[(cc * 9 + dy * 3) * 64 + kt * 4];
#pragma unroll
                for (int dx = 0; dx < 3; ++dx) {
                    ulonglong2 wv = *(const ulonglong2*)(wrow + dx * 64);
                    const u64 w0 = wv.x, w1 = wv.y;
#pragma unroll
                    for (int xi = 0; xi < 4; ++xi) {
                        u64 xv = rp[xi + dx];
                        ffma2(acc[xi][0], xv, w0);
                        ffma2(acc[xi][1], xv, w1);
                    }
                }
            }
        }
        __syncthreads();
    }

    const int gy  = y0 + r;
    const int gxb = x0 + c2 * 4;
#pragma unroll
    for (int kp = 0; kp < 2; ++kp) {
#pragma unroll
        for (int h = 0; h < 2; ++h) {
            int k = k0 + kt * 4 + kp * 2 + h;
            float bv = bias[k];
            float4 o0;
            o0.x = fmaxf(lane(acc[0][kp], h) + bv, 0.f);
            o0.y = fmaxf(lane(acc[1][kp], h) + bv, 0.f);
            o0.z = fmaxf(lane(acc[2][kp], h) + bv, 0.f);
            o0.w = fmaxf(lane(acc[3][kp], h) + bv, 0.f);
            *(float4*)(out + ((size_t)(n * CH + k) * H + gy) * W + gxb) = o0;
        }
    }
}

// ---------------------------------------------------------------------------
// cls final: 1x1 conv 256 -> 80, + bias. One thread per spatial position,
// 80 accumulators in registers; weights staged in 64-channel smem chunks.
// ---------------------------------------------------------------------------
__global__ __launch_bounds__(256)
void final_cls_kernel(const float* __restrict__ x, const float* __restrict__ w,
                      const float* __restrict__ b, float* __restrict__ out,
                      int HW) {
    __shared__ __align__(16) float ws[64 * 84];   // [cc][k], pad 84
    __shared__ float bs[80];
    const int tid = threadIdx.x;
    const int p   = blockIdx.x * 256 + tid;       // grid exact: 4*HW % 256 == 0
    const int n   = p / HW;
    const int hw  = p % HW;
    const float* xb = x + ((size_t)n * CH) * HW + hw;
    if (tid < 80) bs[tid] = b[tid];

    float acc[80];
#pragma unroll
    for (int k = 0; k < 80; ++k) acc[k] = 0.f;

    for (int c0 = 0; c0 < CH; c0 += 64) {
        __syncthreads();
        for (int j = tid; j < 5120; j += 256) {
            int cc = j & 63;
            int k  = j >> 6;
            ws[cc * 84 + k] = w[k * 256 + c0 + cc];
        }
        __syncthreads();
#pragma unroll 4
        for (int cc = 0; cc < 64; ++cc) {
            float xv = xb[(c0 + cc) * HW];
            const float* wr = &ws[cc * 84];
#pragma unroll
            for (int k = 0; k < 80; k += 4) {
                float4 wv = *(const float4*)(wr + k);
                acc[k]     = fmaf(xv, wv.x, acc[k]);
                acc[k + 1] = fmaf(xv, wv.y, acc[k + 1]);
                acc[k + 2] = fmaf(xv, wv.z, acc[k + 2]);
                acc[k + 3] = fmaf(xv, wv.w, acc[k + 3]);
            }
        }
    }
    float* ob = out + ((size_t)n * 80) * HW + hw;
#pragma unroll
    for (int k = 0; k < 80; ++k) ob[(size_t)k * HW] = acc[k] + bs[k];
}

// ---------------------------------------------------------------------------
// reg final: 1x1 conv 256 -> 5, ch0 -> centerness (raw), ch1..4 -> reg with
// *stride then ReLU.
// ---------------------------------------------------------------------------
__global__ __launch_bounds__(256)
void final_reg_kernel(const float* __restrict__ x, const float* __restrict__ w,
                      const float* __restrict__ b, float* __restrict__ out_reg,
                      float* __restrict__ out_ctr, int HW, float sc) {
    __shared__ float ws[256 * 5];
    const int tid = threadIdx.x;
    for (int j = tid; j < 1280; j += 256) {
        int cc = j % 256;
        int k  = j / 256;
        ws[cc * 5 + k] = w[k * 256 + cc];
    }
    __syncthreads();
    const int p  = blockIdx.x * 256 + tid;
    const int n  = p / HW;
    const int hw = p % HW;
    const float* xb = x + ((size_t)n * CH) * HW + hw;
    float a0 = 0.f, a1 = 0.f, a2 = 0.f, a3 = 0.f, a4 = 0.f;
#pragma unroll 4
    for (int c = 0; c < CH; ++c) {
        float xv = xb[c * HW];
        const float* wr = &ws[c * 5];
        a0 = fmaf(xv, wr[0], a0);
        a1 = fmaf(xv, wr[1], a1);
        a2 = fmaf(xv, wr[2], a2);
        a3 = fmaf(xv, wr[3], a3);
        a4 = fmaf(xv, wr[4], a4);
    }
    out_ctr[(size_t)n * HW + hw] = a0 + b[0];
    out_reg[((size_t)n * 4 + 0) * HW + hw] = fmaxf((a1 + b[1]) * sc, 0.f);
    out_reg[((size_t)n * 4 + 1) * HW + hw] = fmaxf((a2 + b[2]) * sc, 0.f);
    out_reg[((size_t)n * 4 + 2) * HW + hw] = fmaxf((a3 + b[3]) * sc, 0.f);
    out_reg[((size_t)n * 4 + 3) * HW + hw] = fmaxf((a4 + b[4]) * sc, 0.f);
}

// ---------------------------------------------------------------------------
// Host launcher (graph-capturable: kernel launches only).
// ---------------------------------------------------------------------------
extern "C" void kernel_launch(void* const* d_in, const int* in_sizes, int n_in,
                              void* d_out, int out_size) {
    const float* fpn[5];
    for (int i = 0; i < 5; ++i) fpn[i] = (const float*)d_in[i];
    const float* cls_conv_w   = (const float*)d_in[5];
    const float* cls_bn_scale = (const float*)d_in[6];
    const float* cls_bn_bias  = (const float*)d_in[7];
    const float* cls_final_w  = (const float*)d_in[8];
    const float* cls_final_b  = (const float*)d_in[9];
    const float* reg_conv_w   = (const float*)d_in[10];
    const float* reg_bn_scale = (const float*)d_in[11];
    const float* reg_bn_bias  = (const float*)d_in[12];
    const float* reg_final_w  = (const float*)d_in[13];
    const float* reg_final_b  = (const float*)d_in[14];
    float* out = (float*)d_out;

    float *bufA, *bufB, *wt;
    cudaGetSymbolAddress((void**)&bufA, g_bufA);
    cudaGetSymbolAddress((void**)&bufB, g_bufB);
    cudaGetSymbolAddress((void**)&wt,   g_wt);

    // Fold BN scale into 3x3 weights + transpose. 4,718,592 / 256 = 18,432 CTAs.
    fold_weights_kernel<<<18432, 256>>>(cls_conv_w, cls_bn_scale,
                                        reg_conv_w, reg_bn_scale);

    const int   Hs[5]  = {128, 64, 32, 16, 8};
    const float scs[5] = {8.f, 16.f, 32.f, 64.f, 128.f};

    size_t cls_off[5], reg_off[5], ctr_off[5];
    size_t a = 0;
    for (int l = 0; l < 5; ++l) { cls_off[l] = a; a += (size_t)4 * 80 * Hs[l] * Hs[l]; }
    for (int l = 0; l < 5; ++l) { reg_off[l] = a; a += (size_t)4 * 4  * Hs[l] * Hs[l]; }
    for (int l = 0; l < 5; ++l) { ctr_off[l] = a; a += (size_t)4 * 1  * Hs[l] * Hs[l]; }

    for (int l = 0; l < 5; ++l) {
        const int H = Hs[l], W = Hs[l], HW = H * W;
        for (int head = 0; head < 2; ++head) {
            const float* bias_base = head ? reg_bn_bias : cls_bn_bias;
            float* bufs[2] = {bufA, bufB};
            for (int L = 0; L < 4; ++L) {
                const float* src = (L == 0) ? fpn[l] : bufs[(L + 1) & 1];
                float*       dst = bufs[L & 1];
                const float* wL  = wt + (size_t)(head * 4 + L) * 2304 * 256;
                if (l < 2) {
                    dim3 grid(W / 16, H / 8, 8);     // 4 batch x 2 k-tiles
                    conv3x3_big<<<grid, 256>>>(src, dst, wL, bias_base + L * 256, H, W);
                } else {
                    dim3 grid(W / 8, H / 8, 16);     // 4 batch x 4 k-tiles
                    conv3x3_small<<<grid, 256>>>(src, dst, wL, bias_base + L * 256, H, W);
                }
            }
            const int PB = (4 * HW) / 256;           // always exact
            if (head == 0)
                final_cls_kernel<<<PB, 256>>>(bufB, cls_final_w, cls_final_b,
                                              out + cls_off[l], HW);
            else
                final_reg_kernel<<<PB, 256>>>(bufB, reg_final_w, reg_final_b,
                                              out + reg_off[l], out + ctr_off[l],
                                              HW, scs[l]);
        }
    }
}

// round 16
// speedup vs baseline: 2.9835x; 2.9835x over previous
#include <cuda_runtime.h>
#include <cuda_bf16.h>
#include <cstdint>

#define CH 256
typedef unsigned long long u64;
typedef unsigned int u32;
typedef __nv_bfloat16 bf16;

// tcgen05 is an sm_103a ("a"-feature) instruction set. The harness also runs a
// plain sm_103 ptxas pass; guard so that pass compiles a stub.
#if defined(__CUDA_ARCH_FEAT_SM103_ALL) || defined(__CUDA_ARCH_SPECIFIC__)
#define TC_OK 1
#else
#define TC_OK 0
#endif

// ---------------- device scratch (allocation-free) -------------------------
__device__ float g_bufA[4 * 256 * 128 * 128];
__device__ float g_bufB[4 * 256 * 128 * 128];
__device__ float g_wt[2 * 4 * 2304 * 256];      // f32 folded (SIMT levels 2-4)
#define PAD0 (4 * 130 * 130 * 256)
__device__ bf16 g_xh[PAD0], g_xl[PAD0], g_yh[PAD0], g_yl[PAD0];
__device__ bf16 g_wbh[2 * 4 * 36 * 256 * 64];   // [head*4+L][blk][k][c64] hi
__device__ bf16 g_wbl[2 * 4 * 36 * 256 * 64];   // lo

// ---------------- helpers ---------------------------------------------------
__device__ __forceinline__ u32 smem_u32(const void* p) {
    u32 a;
    asm("{ .reg .u64 t; cvta.to.shared.u64 t, %1; cvt.u32.u64 %0, t; }" : "=r"(a) : "l"(p));
    return a;
}
#define SW128(o) ((o) ^ (((o) >> 3) & 0x70))
__device__ __forceinline__ void cp16(u32 sa, const void* gp) {
    asm volatile("cp.async.cg.shared.global [%0], [%1], 16;" :: "r"(sa), "l"(gp));
}
#define MBARRIER_INIT(a, c) \
    asm volatile("mbarrier.init.shared.b64 [%0], %1;" :: "r"((u32)(a)), "r"((u32)(c)) : "memory")
#define MBARRIER_WAIT_PARITY(a, par) do { \
    u32 _m = (u32)(a); u32 _p = (u32)(par); u32 _d; \
    asm volatile("{\n\t.reg .pred p;\n\t" \
        "mbarrier.try_wait.parity.acquire.cta.shared::cta.b64 p, [%1], %2;\n\t" \
        "selp.b32 %0, 1, 0, p;\n\t}" : "=r"(_d) : "r"(_m), "r"(_p) : "memory"); \
    if (!_d) { \
        asm volatile("{\n\t.reg .pred P1;\n\t" \
            "WL_%=:\n\t" \
            "mbarrier.try_wait.parity.acquire.cta.shared::cta.b64 P1, [%0], %1, 0x989680;\n\t" \
            "@P1 bra.uni WD_%=;\n\t" \
            "bra.uni WL_%=;\n\t" \
            "WD_%=:\n\t}" :: "r"(_m), "r"(_p) : "memory"); \
    } \
} while (0)

__device__ __forceinline__ void ffma2(u64& d, u64 a, u64 b) {
    asm("fma.rn.f32x2 %0, %1, %2, %0;" : "+l"(d) : "l"(a), "l"(b));
}
__device__ __forceinline__ u64 pack2(float x) {
    unsigned xi = __float_as_uint(x);
    u64 r;
    asm("mov.b64 %0, {%1, %1};" : "=l"(r) : "r"(xi));
    return r;
}
__device__ __forceinline__ float lanef(u64 v, int h) {
    float2 f = *reinterpret_cast<const float2*>(&v);
    return h ? f.y : f.x;
}

#if TC_OK
__device__ __forceinline__ u32 elect1() {
    u32 p;
    asm volatile("{ .reg .pred p; elect.sync _|p, 0xFFFFFFFF; selp.b32 %0,1,0,p; }" : "=r"(p));
    return p;
}
__device__ __forceinline__ u64 make_desc(u32 addr) {   // SW128 K-major
    return (2ull << 61) | (1ull << 46) | (64ull << 32) | (1ull << 16)
         | ((u64)(addr >> 4) & 0x3FFF);
}
__device__ __forceinline__ void mma_f16_ss(u32 d, u64 ad, u64 bd, u32 idesc, bool acc) {
    u32 e = acc ? 1u : 0u;
    asm volatile(
        "{\n\t.reg .pred p;\n\tsetp.ne.u32 p, %4, 0;\n\t"
        "tcgen05.mma.cta_group::1.kind::f16 [%0], %1, %2, %3, {%5,%5,%5,%5}, p;\n\t}"
        :: "r"(d), "l"(ad), "l"(bd), "r"(idesc), "r"(e), "r"(0u) : "memory");
}
#define TCGEN05_ALLOC(sa, n) \
    asm volatile("tcgen05.alloc.cta_group::1.sync.aligned.shared::cta.b32 [%0], %1;" \
                 :: "r"((u32)(sa)), "r"((u32)(n)) : "memory")
#define TCGEN05_DEALLOC(t, n) \
    asm volatile("tcgen05.dealloc.cta_group::1.sync.aligned.b32 %0, %1;" :: "r"(t), "r"((u32)(n)))
#define TCGEN05_WAIT_LD() asm volatile("tcgen05.wait::ld.sync.aligned;" ::: "memory")
#define TCGEN05_FENCE_AFTER() asm volatile("tcgen05.fence::after_thread_sync;" ::: "memory")
#define TCGEN05_LD_X32(r, ta) \
    asm volatile("tcgen05.ld.sync.aligned.32x32b.x32.b32 " \
        "{%0, %1, %2, %3, %4, %5, %6, %7, " \
        " %8, %9, %10, %11, %12, %13, %14, %15, " \
        " %16, %17, %18, %19, %20, %21, %22, %23, " \
        " %24, %25, %26, %27, %28, %29, %30, %31}, [%32];" \
        : "=r"((r)[0]),  "=r"((r)[1]),  "=r"((r)[2]),  "=r"((r)[3]), \
          "=r"((r)[4]),  "=r"((r)[5]),  "=r"((r)[6]),  "=r"((r)[7]), \
          "=r"((r)[8]),  "=r"((r)[9]),  "=r"((r)[10]), "=r"((r)[11]), \
          "=r"((r)[12]), "=r"((r)[13]), "=r"((r)[14]), "=r"((r)[15]), \
          "=r"((r)[16]), "=r"((r)[17]), "=r"((r)[18]), "=r"((r)[19]), \
          "=r"((r)[20]), "=r"((r)[21]), "=r"((r)[22]), "=r"((r)[23]), \
          "=r"((r)[24]), "=r"((r)[25]), "=r"((r)[26]), "=r"((r)[27]), \
          "=r"((r)[28]), "=r"((r)[29]), "=r"((r)[30]), "=r"((r)[31]) \
        : "r"(ta))
#endif  // TC_OK

// ---------------- weight folds ---------------------------------------------
__global__ void fold_weights_kernel(const float* __restrict__ cls_w,
                                    const float* __restrict__ cls_s,
                                    const float* __restrict__ reg_w,
                                    const float* __restrict__ reg_s) {
    int o = blockIdx.x * 256 + threadIdx.x;
    int k = o & 255;
    int rest = o >> 8;
    int t = rest % 9;
    int q = rest / 9;
    int c = q & 255;
    int q2 = q >> 8;
    int L = q2 & 3;
    int head = q2 >> 2;
    const float* w = head ? reg_w : cls_w;
    const float* s = head ? reg_s : cls_s;
    g_wt[o] = w[((L * 256 + k) * 256 + c) * 9 + t] * s[L * 256 + k];
}

__global__ void fold_weights_bf16(const float* __restrict__ cls_w,
                                  const float* __restrict__ cls_s,
                                  const float* __restrict__ reg_w,
                                  const float* __restrict__ reg_s) {
    int o = blockIdx.x * 256 + threadIdx.x;      // 4,718,592 total
    int cc = o & 63;
    int t1 = o >> 6;
    int k = t1 & 255;
    int t2 = t1 >> 8;
    int blk = t2 % 36;
    int hl = t2 / 36;
    int L = hl & 3;
    int head = hl >> 2;
    int tap = blk >> 2, chunk = blk & 3;
    int c = chunk * 64 + cc;
    const float* w = head ? reg_w : cls_w;
    const float* s = head ? reg_s : cls_s;
    float v = w[((L * 256 + k) * 256 + c) * 9 + tap] * s[L * 256 + k];
    bf16 h = __float2bfloat16(v);
    g_wbh[o] = h;
    g_wbl[o] = __float2bfloat16(v - __bfloat162float(h));
}

__global__ void zero_k(uint4* p, int n) {
    int i = blockIdx.x * 256 + threadIdx.x;
    if (i < n) p[i] = make_uint4(0, 0, 0, 0);
}

// NCHW f32 -> padded NHWC bf16 hi/lo
template<int H, int W>
__global__ void transpose_in(const float* __restrict__ in,
                             bf16* __restrict__ oh, bf16* __restrict__ ol) {
    constexpr int PW = W + 2;
    __shared__ float sm[64 * 33];
    int tid = threadIdx.x;
    int x0 = blockIdx.x * 32, y = blockIdx.y;
    int n = blockIdx.z >> 2, cg = blockIdx.z & 3;
    for (int i = tid; i < 2048; i += 256) {
        int c = i >> 5, x = i & 31;
        sm[c * 33 + x] = in[((size_t)(n * 256 + cg * 64 + c) * H + y) * W + x0 + x];
    }
    __syncthreads();
    for (int i = tid; i < 2048; i += 256) {
        int x = i >> 6, c = i & 63;
        float v = sm[c * 33 + x];
        bf16 h = __float2bfloat16(v);
        size_t o = ((size_t)((n * (H + 2) + y + 1) * PW) + x0 + x + 1) * 256 + cg * 64 + c;
        oh[o] = h;
        ol[o] = __float2bfloat16(v - __bfloat162float(h));
    }
}

// ---------------------------------------------------------------------------
// tcgen05 conv3x3: tile = 128 pixels x 256 out-ch; 36 K-blocks x 3 splits.
// ---------------------------------------------------------------------------
#define TC_SMEM (2048 + 2 * 98304)

template<int H, int W>
__global__ __launch_bounds__(256, 1) __cluster_dims__(1, 1, 1)
void conv3_tc(const bf16* __restrict__ Xh, const bf16* __restrict__ Xl,
              bf16* __restrict__ Yh, bf16* __restrict__ Yl,
              float* __restrict__ Yf, int last, int wsel,
              const float* __restrict__ bias) {
#if TC_OK
    constexpr int PW = W + 2;
    extern __shared__ __align__(1024) char smem[];
    const u32 sb = smem_u32(smem);
    const int tid = threadIdx.x, wid = tid >> 5, lid = tid & 31;
    float* bias_s = (float*)(smem + 1024);
    bias_s[tid] = bias[tid];
    if (tid == 0) { MBARRIER_INIT(sb + 8, 1); MBARRIER_INIT(sb + 16, 1); }
    if (wid == 4) TCGEN05_ALLOC(sb + 0, 256);
    __syncthreads();
    u32 tmem;
    asm volatile("ld.shared.b32 %0, [%1];" : "=r"(tmem) : "r"(sb + 0));
    const u32 idesc = (1u << 4) | (1u << 7) | (1u << 10) | (16u << 17) | (8u << 24);

    int ph0 = 0, ph1 = 0;
    for (int b = 0; b < 36; ++b) {
        const int tap = b >> 2, chunk = b & 3, dy = tap / 3, dx = tap % 3;
        const u32 stage = sb + 2048 + (b & 1) * 98304;
        if (b >= 2) {
            if (b & 1) { MBARRIER_WAIT_PARITY(sb + 16, ph1 & 1); ph1++; }
            else       { MBARRIER_WAIT_PARITY(sb + 8,  ph0 & 1); ph0++; }
        }
        // A: 128 pixel rows x 128B x 2 splits
#pragma unroll
        for (int it = 0; it < 8; ++it) {
            int i = tid + it * 256;
            int split = i >> 10, a = i & 1023, row = a >> 3, u = a & 7;
            int g = blockIdx.x * 128 + row;
            int n = g / (H * W), rem = g % (H * W), y = rem / W, x = rem % W;
            const bf16* src = split ? Xl : Xh;
            const bf16* gp = src + ((size_t)((n * (H + 2) + y + dy) * PW) + x + dx) * 256
                           + chunk * 64 + u * 8;
            cp16(stage + split * 16384 + SW128(row * 128 + u * 16), gp);
        }
        // B: 256 k rows x 128B x 2 splits
#pragma unroll
        for (int it = 0; it < 16; ++it) {
            int i = tid + it * 256;
            int split = i >> 11, bi = i & 2047, k = bi >> 3, u = bi & 7;
            const bf16* ws = split ? g_wbl : g_wbh;
            const bf16* gp = ws + ((size_t)(wsel * 36 + b) * 256 + k) * 64 + u * 8;
            cp16(stage + 32768 + split * 32768 + SW128(k * 128 + u * 16), gp);
        }
        asm volatile("cp.async.commit_group;" ::: "memory");
        asm volatile("cp.async.wait_group 0;" ::: "memory");
        __syncthreads();
        if (wid == 4 && elect1()) {
            asm volatile("fence.proxy.async.shared::cta;" ::: "memory");
            u64 Ah = make_desc(stage), Al = make_desc(stage + 16384);
            u64 Bh = make_desc(stage + 32768), Bl = make_desc(stage + 65536);
#pragma unroll
            for (int hf = 0; hf < 2; ++hf) {
                u32 d = tmem + hf * 128;
                u64 bo = hf * 1024;           // +16KB in 16B units
#pragma unroll
                for (int ks = 0; ks < 4; ++ks)
                    mma_f16_ss(d, Ah + ks * 2, Bh + bo + ks * 2, idesc, !(b == 0 && ks == 0));
#pragma unroll
                for (int ks = 0; ks < 4; ++ks)
                    mma_f16_ss(d, Al + ks * 2, Bh + bo + ks * 2, idesc, true);
#pragma unroll
                for (int ks = 0; ks < 4; ++ks)
                    mma_f16_ss(d, Ah + ks * 2, Bl + bo + ks * 2, idesc, true);
            }
            asm volatile(
                "tcgen05.commit.cta_group::1.mbarrier::arrive::one.shared::cluster.b64 [%0];"
                :: "r"(sb + 8 + (b & 1) * 8) : "memory");
        }
    }
    MBARRIER_WAIT_PARITY(sb + 8,  ph0 & 1);
    MBARRIER_WAIT_PARITY(sb + 16, ph1 & 1);
    TCGEN05_FENCE_AFTER();

    if (wid < 4) {
        int pix = blockIdx.x * 128 + wid * 32 + lid;
        int n = pix / (H * W), rem = pix % (H * W), y = rem / W, x = rem % W;
#pragma unroll 1
        for (int ch = 0; ch < 8; ++ch) {
            u32 r[32];
            TCGEN05_LD_X32(r, tmem + ch * 32);
            TCGEN05_WAIT_LD();
            if (last) {
#pragma unroll
                for (int j = 0; j < 32; ++j) {
                    int k = ch * 32 + j;
                    Yf[((size_t)(n * 256 + k) * H + y) * W + x] =
                        fmaxf(__uint_as_float(r[j]) + bias_s[k], 0.f);
                }
            } else {
                size_t po = ((size_t)((n * (H + 2) + y + 1) * PW) + x + 1) * 256 + ch * 32;
#pragma unroll
                for (int j = 0; j < 32; j += 2) {
                    float v0 = fmaxf(__uint_as_float(r[j])     + bias_s[ch * 32 + j],     0.f);
                    float v1 = fmaxf(__uint_as_float(r[j + 1]) + bias_s[ch * 32 + j + 1], 0.f);
                    bf16 h0 = __float2bfloat16(v0), h1 = __float2bfloat16(v1);
                    float l0 = v0 - __bfloat162float(h0), l1 = v1 - __bfloat162float(h1);
                    u32 hp = (u32)__bfloat16_as_ushort(h0) | ((u32)__bfloat16_as_ushort(h1) << 16);
                    u32 lp = (u32)__bfloat16_as_ushort(__float2bfloat16(l0))
                           | ((u32)__bfloat16_as_ushort(__float2bfloat16(l1)) << 16);
                    *reinterpret_cast<u32*>(Yh + po + j) = hp;
                    *reinterpret_cast<u32*>(Yl + po + j) = lp;
                }
            }
        }
    }
    __syncthreads();
    if (wid == 4) TCGEN05_DEALLOC(tmem, 256);
#endif  // TC_OK
}

// ---------------------------------------------------------------------------
// SIMT conv3x3 (levels 2..4), FFMA2 core — unchanged from R9 best.
// ---------------------------------------------------------------------------
__global__ __launch_bounds__(256, 2)
void conv3x3_small(const float* __restrict__ in, float* __restrict__ out,
                   const float* __restrict__ wt, const float* __restrict__ bias,
                   int H, int W) {
    __shared__ __align__(16) float in_s[8 * 10 * 12];
    __shared__ __align__(16) float w_s[72 * 64];
    const int tid = threadIdx.x;
    const int st = tid & 15;
    const int kt = tid >> 4;
    const int r = st & 7;
    const int c2 = st >> 3;
    const int x0 = blockIdx.x * 8;
    const int y0 = blockIdx.y * 8;
    const int n = blockIdx.z >> 2;
    const int k0 = (blockIdx.z & 3) * 64;
    const float* inb = in + ((size_t)n * CH) * H * W;

    u64 acc[4][2];
#pragma unroll
    for (int a = 0; a < 4; ++a)
#pragma unroll
        for (int b = 0; b < 2; ++b) acc[a][b] = 0ull;

    for (int c0 = 0; c0 < CH; c0 += 8) {
        for (int i = tid; i < 800; i += 256) {
            int x = i % 10;
            int yq = i / 10;
            int y = yq % 10;
            int cc = yq / 10;
            int iy = y0 - 1 + y;
            int ix = x0 - 1 + x;
            float v = 0.f;
            if ((unsigned)iy < (unsigned)H && (unsigned)ix < (unsigned)W)
                v = inb[((c0 + cc) * H + iy) * W + ix];
            in_s[cc * 120 + y * 12 + x] = v;
        }
        {
            const float* wp = wt + (size_t)(c0 * 9) * 256 + k0;
            for (int j = tid; j < 4608; j += 256) {
                int k = j & 63;
                int q = j >> 6;
                w_s[j] = wp[q * 256 + k];
            }
        }
        __syncthreads();
#pragma unroll
        for (int cc = 0; cc < 8; ++cc) {
#pragma unroll
            for (int dy = 0; dy < 3; ++dy) {
                const float* rowp = &in_s[cc * 120 + (r + dy) * 12 + c2 * 4];
                float4 a0 = *(const float4*)rowp;
                u64 rp[6];
                rp[0] = pack2(a0.x); rp[1] = pack2(a0.y);
                rp[2] = pack2(a0.z); rp[3] = pack2(a0.w);
                rp[4] = pack2(rowp[4]); rp[5] = pack2(rowp[5]);
                const float* wrow = &w_s[(cc * 9 + dy * 3) * 64 + kt * 4];
#pragma unroll
                for (int dx = 0; dx < 3; ++dx) {
                    ulonglong2 wv = *(const ulonglong2*)(wrow + dx * 64);
                    const u64 w0 = wv.x, w1 = wv.y;
#pragma unroll
                    for (int xi = 0; xi < 4; ++xi) {
                        u64 xv = rp[xi + dx];
                        ffma2(acc[xi][0], xv, w0);
                        ffma2(acc[xi][1], xv, w1);
                    }
                }
            }
        }
        __syncthreads();
    }
    const int gy = y0 + r;
    const int gxb = x0 + c2 * 4;
#pragma unroll
    for (int kp = 0; kp < 2; ++kp) {
#pragma unroll
        for (int h = 0; h < 2; ++h) {
            int k = k0 + kt * 4 + kp * 2 + h;
            float bv = bias[k];
            float4 o0;
            o0.x = fmaxf(lanef(acc[0][kp], h) + bv, 0.f);
            o0.y = fmaxf(lanef(acc[1][kp], h) + bv, 0.f);
            o0.z = fmaxf(lanef(acc[2][kp], h) + bv, 0.f);
            o0.w = fmaxf(lanef(acc[3][kp], h) + bv, 0.f);
            *(float4*)(out + ((size_t)(n * CH + k) * H + gy) * W + gxb) = o0;
        }
    }
}

// ---------------- final 1x1 heads (NCHW input) -----------------------------
__global__ __launch_bounds__(256)
void final_cls_kernel(const float* __restrict__ x, const float* __restrict__ w,
                      const float* __restrict__ b, float* __restrict__ out, int HW) {
    __shared__ __align__(16) float ws[64 * 84];
    __shared__ float bs[80];
    const int tid = threadIdx.x;
    const int p = blockIdx.x * 256 + tid;
    const int n = p / HW;
    const int hw = p % HW;
    const float* xb = x + ((size_t)n * CH) * HW + hw;
    if (tid < 80) bs[tid] = b[tid];
    float acc[80];
#pragma unroll
    for (int k = 0; k < 80; ++k) acc[k] = 0.f;
    for (int c0 = 0; c0 < CH; c0 += 64) {
        __syncthreads();
        for (int j = tid; j < 5120; j += 256) {
            int cc = j & 63;
            int k = j >> 6;
            ws[cc * 84 + k] = w[k * 256 + c0 + cc];
        }
        __syncthreads();
#pragma unroll 4
        for (int cc = 0; cc < 64; ++cc) {
            float xv = xb[(c0 + cc) * HW];
            const float* wr = &ws[cc * 84];
#pragma unroll
            for (int k = 0; k < 80; k += 4) {
                float4 wv = *(const float4*)(wr + k);
                acc[k]     = fmaf(xv, wv.x, acc[k]);
                acc[k + 1] = fmaf(xv, wv.y, acc[k + 1]);
                acc[k + 2] = fmaf(xv, wv.z, acc[k + 2]);
                acc[k + 3] = fmaf(xv, wv.w, acc[k + 3]);
            }
        }
    }
    float* ob = out + ((size_t)n * 80) * HW + hw;
#pragma unroll
    for (int k = 0; k < 80; ++k) ob[(size_t)k * HW] = acc[k] + bs[k];
}

__global__ __launch_bounds__(256)
void final_reg_kernel(const float* __restrict__ x, const float* __restrict__ w,
                      const float* __restrict__ b, float* __restrict__ out_reg,
                      float* __restrict__ out_ctr, int HW, float sc) {
    __shared__ float ws[256 * 5];
    const int tid = threadIdx.x;
    for (int j = tid; j < 1280; j += 256) {
        int cc = j % 256;
        int k = j / 256;
        ws[cc * 5 + k] = w[k * 256 + cc];
    }
    __syncthreads();
    const int p = blockIdx.x * 256 + tid;
    const int n = p / HW;
    const int hw = p % HW;
    const float* xb = x + ((size_t)n * CH) * HW + hw;
    float a0 = 0.f, a1 = 0.f, a2 = 0.f, a3 = 0.f, a4 = 0.f;
#pragma unroll 4
    for (int c = 0; c < CH; ++c) {
        float xv = xb[c * HW];
        const float* wr = &ws[c * 5];
        a0 = fmaf(xv, wr[0], a0);
        a1 = fmaf(xv, wr[1], a1);
        a2 = fmaf(xv, wr[2], a2);
        a3 = fmaf(xv, wr[3], a3);
        a4 = fmaf(xv, wr[4], a4);
    }
    out_ctr[(size_t)n * HW + hw] = a0 + b[0];
    out_reg[((size_t)n * 4 + 0) * HW + hw] = fmaxf((a1 + b[1]) * sc, 0.f);
    out_reg[((size_t)n * 4 + 1) * HW + hw] = fmaxf((a2 + b[2]) * sc, 0.f);
    out_reg[((size_t)n * 4 + 2) * HW + hw] = fmaxf((a3 + b[3]) * sc, 0.f);
    out_reg[((size_t)n * 4 + 3) * HW + hw] = fmaxf((a4 + b[4]) * sc, 0.f);
}

// ---------------------------------------------------------------------------
// Host launcher (graph-capturable: kernel launches only).
// ---------------------------------------------------------------------------
extern "C" void kernel_launch(void* const* d_in, const int* in_sizes, int n_in,
                              void* d_out, int out_size) {
    const float* fpn[5];
    for (int i = 0; i < 5; ++i) fpn[i] = (const float*)d_in[i];
    const float* cls_conv_w   = (const float*)d_in[5];
    const float* cls_bn_scale = (const float*)d_in[6];
    const float* cls_bn_bias  = (const float*)d_in[7];
    const float* cls_final_w  = (const float*)d_in[8];
    const float* cls_final_b  = (const float*)d_in[9];
    const float* reg_conv_w   = (const float*)d_in[10];
    const float* reg_bn_scale = (const float*)d_in[11];
    const float* reg_bn_bias  = (const float*)d_in[12];
    const float* reg_final_w  = (const float*)d_in[13];
    const float* reg_final_b  = (const float*)d_in[14];
    float* out = (float*)d_out;

    float *bufA, *bufB, *wt;
    bf16 *xh, *xl, *yh, *yl;
    cudaGetSymbolAddress((void**)&bufA, g_bufA);
    cudaGetSymbolAddress((void**)&bufB, g_bufB);
    cudaGetSymbolAddress((void**)&wt,   g_wt);
    cudaGetSymbolAddress((void**)&xh, g_xh);
    cudaGetSymbolAddress((void**)&xl, g_xl);
    cudaGetSymbolAddress((void**)&yh, g_yh);
    cudaGetSymbolAddress((void**)&yl, g_yl);

    cudaFuncSetAttribute(conv3_tc<128, 128>,
                         cudaFuncAttributeMaxDynamicSharedMemorySize, TC_SMEM);
    cudaFuncSetAttribute(conv3_tc<64, 64>,
                         cudaFuncAttributeMaxDynamicSharedMemorySize, TC_SMEM);

    fold_weights_kernel<<<18432, 256>>>(cls_conv_w, cls_bn_scale, reg_conv_w, reg_bn_scale);
    fold_weights_bf16<<<18432, 256>>>(cls_conv_w, cls_bn_scale, reg_conv_w, reg_bn_scale);

    const int   Hs[5]  = {128, 64, 32, 16, 8};
    const float scs[5] = {8.f, 16.f, 32.f, 64.f, 128.f};
    size_t cls_off[5], reg_off[5], ctr_off[5];
    size_t a = 0;
    for (int l = 0; l < 5; ++l) { cls_off[l] = a; a += (size_t)4 * 80 * Hs[l] * Hs[l]; }
    for (int l = 0; l < 5; ++l) { reg_off[l] = a; a += (size_t)4 * 4  * Hs[l] * Hs[l]; }
    for (int l = 0; l < 5; ++l) { ctr_off[l] = a; a += (size_t)4 * 1  * Hs[l] * Hs[l]; }

    // zero padded activation buffers (level-0 footprint)
    {
        int n0 = PAD0 * 2 / 16;            // uint4 count
        int g0 = (n0 + 255) / 256;
        zero_k<<<g0, 256>>>((uint4*)xh, n0);
        zero_k<<<g0, 256>>>((uint4*)xl, n0);
        zero_k<<<g0, 256>>>((uint4*)yh, n0);
        zero_k<<<g0, 256>>>((uint4*)yl, n0);
    }

    // ---- levels 0,1: tcgen05 path ----
    for (int l = 0; l < 2; ++l) {
        const int H = Hs[l], W = Hs[l], HW = H * W;
        if (l == 1) {                       // re-zero level-1 footprint (layout change)
            int n1 = 4 * 66 * 66 * 256 * 2 / 16;
            int g1 = (n1 + 255) / 256;
            zero_k<<<g1, 256>>>((uint4*)xh, n1);
            zero_k<<<g1, 256>>>((uint4*)xl, n1);
            zero_k<<<g1, 256>>>((uint4*)yh, n1);
            zero_k<<<g1, 256>>>((uint4*)yl, n1);
        }
        for (int head = 0; head < 2; ++head) {
            const float* bnb = head ? reg_bn_bias : cls_bn_bias;
            dim3 tg(W / 32, H, 16);
            int tiles = 4 * HW / 128;
            if (l == 0) {
                transpose_in<128, 128><<<tg, 256>>>(fpn[l], xh, xl);
                conv3_tc<128, 128><<<tiles, 256, TC_SMEM>>>(xh, xl, yh, yl, bufB, 0, head * 4 + 0, bnb + 0);
                conv3_tc<128, 128><<<tiles, 256, TC_SMEM>>>(yh, yl, xh, xl, bufB, 0, head * 4 + 1, bnb + 256);
                conv3_tc<128, 128><<<tiles, 256, TC_SMEM>>>(xh, xl, yh, yl, bufB, 0, head * 4 + 2, bnb + 512);
                conv3_tc<128, 128><<<tiles, 256, TC_SMEM>>>(yh, yl, xh, xl, bufB, 1, head * 4 + 3, bnb + 768);
            } else {
                transpose_in<64, 64><<<tg, 256>>>(fpn[l], xh, xl);
                conv3_tc<64, 64><<<tiles, 256, TC_SMEM>>>(xh, xl, yh, yl, bufB, 0, head * 4 + 0, bnb + 0);
                conv3_tc<64, 64><<<tiles, 256, TC_SMEM>>>(yh, yl, xh, xl, bufB, 0, head * 4 + 1, bnb + 256);
                conv3_tc<64, 64><<<tiles, 256, TC_SMEM>>>(xh, xl, yh, yl, bufB, 0, head * 4 + 2, bnb + 512);
                conv3_tc<64, 64><<<tiles, 256, TC_SMEM>>>(yh, yl, xh, xl, bufB, 1, head * 4 + 3, bnb + 768);
            }
            const int PB = (4 * HW) / 256;
            if (head == 0)
                final_cls_kernel<<<PB, 256>>>(bufB, cls_final_w, cls_final_b,
                                              out + cls_off[l], HW);
            else
                final_reg_kernel<<<PB, 256>>>(bufB, reg_final_w, reg_final_b,
                                              out + reg_off[l], out + ctr_off[l], HW, scs[l]);
        }
    }

    // ---- levels 2..4: SIMT path ----
    for (int l = 2; l < 5; ++l) {
        const int H = Hs[l], W = Hs[l], HW = H * W;
        for (int head = 0; head < 2; ++head) {
            const float* bias_base = head ? reg_bn_bias : cls_bn_bias;
            float* bufs[2] = {bufA, bufB};
            for (int L = 0; L < 4; ++L) {
                const float* src = (L == 0) ? fpn[l] : bufs[(L + 1) & 1];
                float*       dst = bufs[L & 1];
                const float* wL  = wt + (size_t)(head * 4 + L) * 2304 * 256;
                dim3 grid(W / 8, H / 8, 16);
                conv3x3_small<<<grid, 256>>>(src, dst, wL, bias_base + L * 256, H, W);
            }
            const int PB = (4 * HW) / 256;
            if (head == 0)
                final_cls_kernel<<<PB, 256>>>(bufB, cls_final_w, cls_final_b,
                                              out + cls_off[l], HW);
            else
                final_reg_kernel<<<PB, 256>>>(bufB, reg_final_w, reg_final_b,
                                              out + reg_off[l], out + ctr_off[l], HW, scs[l]);
        }
    }
}

// round 17
// speedup vs baseline: 2.9863x; 1.0009x over previous
#include <cuda_runtime.h>
#include <cuda_bf16.h>
#include <cstdint>

#define CH 256
typedef unsigned long long u64;
typedef unsigned int u32;
typedef __nv_bfloat16 bf16;

// tcgen05 is an sm_103a ("a"-feature) instruction set. The harness also runs a
// plain sm_103 ptxas pass; guard so that pass compiles a stub.
#if defined(__CUDA_ARCH_FEAT_SM103_ALL) || defined(__CUDA_ARCH_SPECIFIC__)
#define TC_OK 1
#else
#define TC_OK 0
#endif

// ---------------- device scratch (allocation-free) -------------------------
__device__ float g_bufA[4 * 256 * 128 * 128];
__device__ float g_bufB[4 * 256 * 128 * 128];
__device__ float g_wt[2 * 4 * 2304 * 256];      // f32 folded (SIMT levels 2-4)
#define PAD0 (4 * 130 * 130 * 256)
__device__ bf16 g_xh[PAD0], g_xl[PAD0], g_yh[PAD0], g_yl[PAD0];
__device__ bf16 g_wbh[2 * 4 * 36 * 256 * 64];   // [head*4+L][blk][k][c64] hi
__device__ bf16 g_wbl[2 * 4 * 36 * 256 * 64];   // lo

// ---------------- helpers ---------------------------------------------------
__device__ __forceinline__ u32 smem_u32(const void* p) {
    u32 a;
    asm("{ .reg .u64 t; cvta.to.shared.u64 t, %1; cvt.u32.u64 %0, t; }" : "=r"(a) : "l"(p));
    return a;
}
#define SW128(o) ((o) ^ (((o) >> 3) & 0x70))
__device__ __forceinline__ void cp16(u32 sa, const void* gp) {
    asm volatile("cp.async.cg.shared.global [%0], [%1], 16;" :: "r"(sa), "l"(gp));
}
#define MBARRIER_INIT(a, c) \
    asm volatile("mbarrier.init.shared.b64 [%0], %1;" :: "r"((u32)(a)), "r"((u32)(c)) : "memory")
#define MBARRIER_WAIT_PARITY(a, par) do { \
    u32 _m = (u32)(a); u32 _p = (u32)(par); u32 _d; \
    asm volatile("{\n\t.reg .pred p;\n\t" \
        "mbarrier.try_wait.parity.acquire.cta.shared::cta.b64 p, [%1], %2;\n\t" \
        "selp.b32 %0, 1, 0, p;\n\t}" : "=r"(_d) : "r"(_m), "r"(_p) : "memory"); \
    if (!_d) { \
        asm volatile("{\n\t.reg .pred P1;\n\t" \
            "WL_%=:\n\t" \
            "mbarrier.try_wait.parity.acquire.cta.shared::cta.b64 P1, [%0], %1, 0x989680;\n\t" \
            "@P1 bra.uni WD_%=;\n\t" \
            "bra.uni WL_%=;\n\t" \
            "WD_%=:\n\t}" :: "r"(_m), "r"(_p) : "memory"); \
    } \
} while (0)

__device__ __forceinline__ void ffma2(u64& d, u64 a, u64 b) {
    asm("fma.rn.f32x2 %0, %1, %2, %0;" : "+l"(d) : "l"(a), "l"(b));
}
__device__ __forceinline__ u64 pack2(float x) {
    unsigned xi = __float_as_uint(x);
    u64 r;
    asm("mov.b64 %0, {%1, %1};" : "=l"(r) : "r"(xi));
    return r;
}
__device__ __forceinline__ float lanef(u64 v, int h) {
    float2 f = *reinterpret_cast<const float2*>(&v);
    return h ? f.y : f.x;
}

#if TC_OK
__device__ __forceinline__ u32 elect1() {
    u32 p;
    asm volatile("{ .reg .pred p; elect.sync _|p, 0xFFFFFFFF; selp.b32 %0,1,0,p; }" : "=r"(p));
    return p;
}
__device__ __forceinline__ u64 make_desc(u32 addr) {   // SW128 K-major
    return (2ull << 61) | (1ull << 46) | (64ull << 32) | (1ull << 16)
         | ((u64)(addr >> 4) & 0x3FFF);
}
__device__ __forceinline__ void mma_f16_ss(u32 d, u64 ad, u64 bd, u32 idesc, bool acc) {
    u32 e = acc ? 1u : 0u;
    asm volatile(
        "{\n\t.reg .pred p;\n\tsetp.ne.u32 p, %4, 0;\n\t"
        "tcgen05.mma.cta_group::1.kind::f16 [%0], %1, %2, %3, {%5,%5,%5,%5}, p;\n\t}"
        :: "r"(d), "l"(ad), "l"(bd), "r"(idesc), "r"(e), "r"(0u) : "memory");
}
#define TCGEN05_ALLOC(sa, n) \
    asm volatile("tcgen05.alloc.cta_group::1.sync.aligned.shared::cta.b32 [%0], %1;" \
                 :: "r"((u32)(sa)), "r"((u32)(n)) : "memory")
#define TCGEN05_DEALLOC(t, n) \
    asm volatile("tcgen05.dealloc.cta_group::1.sync.aligned.b32 %0, %1;" :: "r"(t), "r"((u32)(n)))
#define TCGEN05_WAIT_LD() asm volatile("tcgen05.wait::ld.sync.aligned;" ::: "memory")
#define TCGEN05_FENCE_AFTER() asm volatile("tcgen05.fence::after_thread_sync;" ::: "memory")
#define TCGEN05_LD_X32(r, ta) \
    asm volatile("tcgen05.ld.sync.aligned.32x32b.x32.b32 " \
        "{%0, %1, %2, %3, %4, %5, %6, %7, " \
        " %8, %9, %10, %11, %12, %13, %14, %15, " \
        " %16, %17, %18, %19, %20, %21, %22, %23, " \
        " %24, %25, %26, %27, %28, %29, %30, %31}, [%32];" \
        : "=r"((r)[0]),  "=r"((r)[1]),  "=r"((r)[2]),  "=r"((r)[3]), \
          "=r"((r)[4]),  "=r"((r)[5]),  "=r"((r)[6]),  "=r"((r)[7]), \
          "=r"((r)[8]),  "=r"((r)[9]),  "=r"((r)[10]), "=r"((r)[11]), \
          "=r"((r)[12]), "=r"((r)[13]), "=r"((r)[14]), "=r"((r)[15]), \
          "=r"((r)[16]), "=r"((r)[17]), "=r"((r)[18]), "=r"((r)[19]), \
          "=r"((r)[20]), "=r"((r)[21]), "=r"((r)[22]), "=r"((r)[23]), \
          "=r"((r)[24]), "=r"((r)[25]), "=r"((r)[26]), "=r"((r)[27]), \
          "=r"((r)[28]), "=r"((r)[29]), "=r"((r)[30]), "=r"((r)[31]) \
        : "r"(ta))
#endif  // TC_OK

// ---------------- weight folds ---------------------------------------------
__global__ void fold_weights_kernel(const float* __restrict__ cls_w,
                                    const float* __restrict__ cls_s,
                                    const float* __restrict__ reg_w,
                                    const float* __restrict__ reg_s) {
    int o = blockIdx.x * 256 + threadIdx.x;
    int k = o & 255;
    int rest = o >> 8;
    int t = rest % 9;
    int q = rest / 9;
    int c = q & 255;
    int q2 = q >> 8;
    int L = q2 & 3;
    int head = q2 >> 2;
    const float* w = head ? reg_w : cls_w;
    const float* s = head ? reg_s : cls_s;
    g_wt[o] = w[((L * 256 + k) * 256 + c) * 9 + t] * s[L * 256 + k];
}

__global__ void fold_weights_bf16(const float* __restrict__ cls_w,
                                  const float* __restrict__ cls_s,
                                  const float* __restrict__ reg_w,
                                  const float* __restrict__ reg_s) {
    int o = blockIdx.x * 256 + threadIdx.x;      // 4,718,592 total
    int cc = o & 63;
    int t1 = o >> 6;
    int k = t1 & 255;
    int t2 = t1 >> 8;
    int blk = t2 % 36;
    int hl = t2 / 36;
    int L = hl & 3;
    int head = hl >> 2;
    int tap = blk >> 2, chunk = blk & 3;
    int c = chunk * 64 + cc;
    const float* w = head ? reg_w : cls_w;
    const float* s = head ? reg_s : cls_s;
    float v = w[((L * 256 + k) * 256 + c) * 9 + tap] * s[L * 256 + k];
    bf16 h = __float2bfloat16(v);
    g_wbh[o] = h;
    g_wbl[o] = __float2bfloat16(v - __bfloat162float(h));
}

__global__ void zero_k(uint4* p, int n) {
    int i = blockIdx.x * 256 + threadIdx.x;
    if (i < n) p[i] = make_uint4(0, 0, 0, 0);
}

// NCHW f32 -> padded NHWC bf16 hi/lo
template<int H, int W>
__global__ void transpose_in(const float* __restrict__ in,
                             bf16* __restrict__ oh, bf16* __restrict__ ol) {
    constexpr int PW = W + 2;
    __shared__ float sm[64 * 33];
    int tid = threadIdx.x;
    int x0 = blockIdx.x * 32, y = blockIdx.y;
    int n = blockIdx.z >> 2, cg = blockIdx.z & 3;
    for (int i = tid; i < 2048; i += 256) {
        int c = i >> 5, x = i & 31;
        sm[c * 33 + x] = in[((size_t)(n * 256 + cg * 64 + c) * H + y) * W + x0 + x];
    }
    __syncthreads();
    for (int i = tid; i < 2048; i += 256) {
        int x = i >> 6, c = i & 63;
        float v = sm[c * 33 + x];
        bf16 h = __float2bfloat16(v);
        size_t o = ((size_t)((n * (H + 2) + y + 1) * PW) + x0 + x + 1) * 256 + cg * 64 + c;
        oh[o] = h;
        ol[o] = __float2bfloat16(v - __bfloat162float(h));
    }
}

// ---------------------------------------------------------------------------
// tcgen05 conv3x3: tile = 128 pixels x 256 out-ch; 36 K-blocks x 3 splits.
// ---------------------------------------------------------------------------
#define TC_SMEM (2048 + 2 * 98304)

template<int H, int W>
__global__ __launch_bounds__(256, 1) __cluster_dims__(1, 1, 1)
void conv3_tc(const bf16* __restrict__ Xh, const bf16* __restrict__ Xl,
              bf16* __restrict__ Yh, bf16* __restrict__ Yl,
              float* __restrict__ Yf, int last, int wsel,
              const float* __restrict__ bias) {
#if TC_OK
    constexpr int PW = W + 2;
    extern __shared__ __align__(1024) char smem[];
    const u32 sb = smem_u32(smem);
    const int tid = threadIdx.x, wid = tid >> 5, lid = tid & 31;
    float* bias_s = (float*)(smem + 1024);
    bias_s[tid] = bias[tid];
    if (tid == 0) { MBARRIER_INIT(sb + 8, 1); MBARRIER_INIT(sb + 16, 1); }
    if (wid == 4) TCGEN05_ALLOC(sb + 0, 256);
    __syncthreads();
    u32 tmem;
    asm volatile("ld.shared.b32 %0, [%1];" : "=r"(tmem) : "r"(sb + 0));
    const u32 idesc = (1u << 4) | (1u << 7) | (1u << 10) | (16u << 17) | (8u << 24);

    int ph0 = 0, ph1 = 0;
    for (int b = 0; b < 36; ++b) {
        const int tap = b >> 2, chunk = b & 3, dy = tap / 3, dx = tap % 3;
        const u32 stage = sb + 2048 + (b & 1) * 98304;
        if (b >= 2) {
            if (b & 1) { MBARRIER_WAIT_PARITY(sb + 16, ph1 & 1); ph1++; }
            else       { MBARRIER_WAIT_PARITY(sb + 8,  ph0 & 1); ph0++; }
        }
        // A: 128 pixel rows x 128B x 2 splits
#pragma unroll
        for (int it = 0; it < 8; ++it) {
            int i = tid + it * 256;
            int split = i >> 10, a = i & 1023, row = a >> 3, u = a & 7;
            int g = blockIdx.x * 128 + row;
            int n = g / (H * W), rem = g % (H * W), y = rem / W, x = rem % W;
            const bf16* src = split ? Xl : Xh;
            const bf16* gp = src + ((size_t)((n * (H + 2) + y + dy) * PW) + x + dx) * 256
                           + chunk * 64 + u * 8;
            cp16(stage + split * 16384 + SW128(row * 128 + u * 16), gp);
        }
        // B: 256 k rows x 128B x 2 splits
#pragma unroll
        for (int it = 0; it < 16; ++it) {
            int i = tid + it * 256;
            int split = i >> 11, bi = i & 2047, k = bi >> 3, u = bi & 7;
            const bf16* ws = split ? g_wbl : g_wbh;
            const bf16* gp = ws + ((size_t)(wsel * 36 + b) * 256 + k) * 64 + u * 8;
            cp16(stage + 32768 + split * 32768 + SW128(k * 128 + u * 16), gp);
        }
        asm volatile("cp.async.commit_group;" ::: "memory");
        asm volatile("cp.async.wait_group 0;" ::: "memory");
        __syncthreads();
        if (wid == 4 && elect1()) {
            asm volatile("fence.proxy.async.shared::cta;" ::: "memory");
            u64 Ah = make_desc(stage), Al = make_desc(stage + 16384);
            u64 Bh = make_desc(stage + 32768), Bl = make_desc(stage + 65536);
#pragma unroll
            for (int hf = 0; hf < 2; ++hf) {
                u32 d = tmem + hf * 128;
                u64 bo = hf * 1024;           // +16KB in 16B units
#pragma unroll
                for (int ks = 0; ks < 4; ++ks)
                    mma_f16_ss(d, Ah + ks * 2, Bh + bo + ks * 2, idesc, !(b == 0 && ks == 0));
#pragma unroll
                for (int ks = 0; ks < 4; ++ks)
                    mma_f16_ss(d, Al + ks * 2, Bh + bo + ks * 2, idesc, true);
#pragma unroll
                for (int ks = 0; ks < 4; ++ks)
                    mma_f16_ss(d, Ah + ks * 2, Bl + bo + ks * 2, idesc, true);
            }
            asm volatile(
                "tcgen05.commit.cta_group::1.mbarrier::arrive::one.shared::cluster.b64 [%0];"
                :: "r"(sb + 8 + (b & 1) * 8) : "memory");
        }
    }
    MBARRIER_WAIT_PARITY(sb + 8,  ph0 & 1);
    MBARRIER_WAIT_PARITY(sb + 16, ph1 & 1);
    TCGEN05_FENCE_AFTER();

    if (wid < 4) {
        int pix = blockIdx.x * 128 + wid * 32 + lid;
        int n = pix / (H * W), rem = pix % (H * W), y = rem / W, x = rem % W;
#pragma unroll 1
        for (int ch = 0; ch < 8; ++ch) {
            u32 r[32];
            TCGEN05_LD_X32(r, tmem + ch * 32);
            TCGEN05_WAIT_LD();
            if (last) {
#pragma unroll
                for (int j = 0; j < 32; ++j) {
                    int k = ch * 32 + j;
                    Yf[((size_t)(n * 256 + k) * H + y) * W + x] =
                        fmaxf(__uint_as_float(r[j]) + bias_s[k], 0.f);
                }
            } else {
                size_t po = ((size_t)((n * (H + 2) + y + 1) * PW) + x + 1) * 256 + ch * 32;
#pragma unroll
                for (int j = 0; j < 32; j += 2) {
                    float v0 = fmaxf(__uint_as_float(r[j])     + bias_s[ch * 32 + j],     0.f);
                    float v1 = fmaxf(__uint_as_float(r[j + 1]) + bias_s[ch * 32 + j + 1], 0.f);
                    bf16 h0 = __float2bfloat16(v0), h1 = __float2bfloat16(v1);
                    float l0 = v0 - __bfloat162float(h0), l1 = v1 - __bfloat162float(h1);
                    u32 hp = (u32)__bfloat16_as_ushort(h0) | ((u32)__bfloat16_as_ushort(h1) << 16);
                    u32 lp = (u32)__bfloat16_as_ushort(__float2bfloat16(l0))
                           | ((u32)__bfloat16_as_ushort(__float2bfloat16(l1)) << 16);
                    *reinterpret_cast<u32*>(Yh + po + j) = hp;
                    *reinterpret_cast<u32*>(Yl + po + j) = lp;
                }
            }
        }
    }
    __syncthreads();
    if (wid == 4) TCGEN05_DEALLOC(tmem, 256);
#endif  // TC_OK
}

// ---------------------------------------------------------------------------
// SIMT conv3x3 (levels 2..4), FFMA2 core — unchanged from R9 best.
// ---------------------------------------------------------------------------
__global__ __launch_bounds__(256, 2)
void conv3x3_small(const float* __restrict__ in, float* __restrict__ out,
                   const float* __restrict__ wt, const float* __restrict__ bias,
                   int H, int W) {
    __shared__ __align__(16) float in_s[8 * 10 * 12];
    __shared__ __align__(16) float w_s[72 * 64];
    const int tid = threadIdx.x;
    const int st = tid & 15;
    const int kt = tid >> 4;
    const int r = st & 7;
    const int c2 = st >> 3;
    const int x0 = blockIdx.x * 8;
    const int y0 = blockIdx.y * 8;
    const int n = blockIdx.z >> 2;
    const int k0 = (blockIdx.z & 3) * 64;
    const float* inb = in + ((size_t)n * CH) * H * W;

    u64 acc[4][2];
#pragma unroll
    for (int a = 0; a < 4; ++a)
#pragma unroll
        for (int b = 0; b < 2; ++b) acc[a][b] = 0ull;

    for (int c0 = 0; c0 < CH; c0 += 8) {
        for (int i = tid; i < 800; i += 256) {
            int x = i % 10;
            int yq = i / 10;
            int y = yq % 10;
            int cc = yq / 10;
            int iy = y0 - 1 + y;
            int ix = x0 - 1 + x;
            float v = 0.f;
            if ((unsigned)iy < (unsigned)H && (unsigned)ix < (unsigned)W)
                v = inb[((c0 + cc) * H + iy) * W + ix];
            in_s[cc * 120 + y * 12 + x] = v;
        }
        {
            const float* wp = wt + (size_t)(c0 * 9) * 256 + k0;
            for (int j = tid; j < 4608; j += 256) {
                int k = j & 63;
                int q = j >> 6;
                w_s[j] = wp[q * 256 + k];
            }
        }
        __syncthreads();
#pragma unroll
        for (int cc = 0; cc < 8; ++cc) {
#pragma unroll
            for (int dy = 0; dy < 3; ++dy) {
                const float* rowp = &in_s[cc * 120 + (r + dy) * 12 + c2 * 4];
                float4 a0 = *(const float4*)rowp;
                u64 rp[6];
                rp[0] = pack2(a0.x); rp[1] = pack2(a0.y);
                rp[2] = pack2(a0.z); rp[3] = pack2(a0.w);
                rp[4] = pack2(rowp[4]); rp[5] = pack2(rowp[5]);
                const float* wrow = &w_s[(cc * 9 + dy * 3) * 64 + kt * 4];
#pragma unroll
                for (int dx = 0; dx < 3; ++dx) {
                    ulonglong2 wv = *(const ulonglong2*)(wrow + dx * 64);
                    const u64 w0 = wv.x, w1 = wv.y;
#pragma unroll
                    for (int xi = 0; xi < 4; ++xi) {
                        u64 xv = rp[xi + dx];
                        ffma2(acc[xi][0], xv, w0);
                        ffma2(acc[xi][1], xv, w1);
                    }
                }
            }
        }
        __syncthreads();
    }
    const int gy = y0 + r;
    const int gxb = x0 + c2 * 4;
#pragma unroll
    for (int kp = 0; kp < 2; ++kp) {
#pragma unroll
        for (int h = 0; h < 2; ++h) {
            int k = k0 + kt * 4 + kp * 2 + h;
            float bv = bias[k];
            float4 o0;
            o0.x = fmaxf(lanef(acc[0][kp], h) + bv, 0.f);
            o0.y = fmaxf(lanef(acc[1][kp], h) + bv, 0.f);
            o0.z = fmaxf(lanef(acc[2][kp], h) + bv, 0.f);
            o0.w = fmaxf(lanef(acc[3][kp], h) + bv, 0.f);
            *(float4*)(out + ((size_t)(n * CH + k) * H + gy) * W + gxb) = o0;
        }
    }
}

// ---------------- final 1x1 heads (NCHW input) -----------------------------
__global__ __launch_bounds__(256)
void final_cls_kernel(const float* __restrict__ x, const float* __restrict__ w,
                      const float* __restrict__ b, float* __restrict__ out, int HW) {
    __shared__ __align__(16) float ws[64 * 84];
    __shared__ float bs[80];
    const int tid = threadIdx.x;
    const int p = blockIdx.x * 256 + tid;
    const int n = p / HW;
    const int hw = p % HW;
    const float* xb = x + ((size_t)n * CH) * HW + hw;
    if (tid < 80) bs[tid] = b[tid];
    float acc[80];
#pragma unroll
    for (int k = 0; k < 80; ++k) acc[k] = 0.f;
    for (int c0 = 0; c0 < CH; c0 += 64) {
        __syncthreads();
        for (int j = tid; j < 5120; j += 256) {
            int cc = j & 63;
            int k = j >> 6;
            ws[cc * 84 + k] = w[k * 256 + c0 + cc];
        }
        __syncthreads();
#pragma unroll 4
        for (int cc = 0; cc < 64; ++cc) {
            float xv = xb[(c0 + cc) * HW];
            const float* wr = &ws[cc * 84];
#pragma unroll
            for (int k = 0; k < 80; k += 4) {
                float4 wv = *(const float4*)(wr + k);
                acc[k]     = fmaf(xv, wv.x, acc[k]);
                acc[k + 1] = fmaf(xv, wv.y, acc[k + 1]);
                acc[k + 2] = fmaf(xv, wv.z, acc[k + 2]);
                acc[k + 3] = fmaf(xv, wv.w, acc[k + 3]);
            }
        }
    }
    float* ob = out + ((size_t)n * 80) * HW + hw;
#pragma unroll
    for (int k = 0; k < 80; ++k) ob[(size_t)k * HW] = acc[k] + bs[k];
}

__global__ __launch_bounds__(256)
void final_reg_kernel(const float* __restrict__ x, const float* __restrict__ w,
                      const float* __restrict__ b, float* __restrict__ out_reg,
                      float* __restrict__ out_ctr, int HW, float sc) {
    __shared__ float ws[256 * 5];
    const int tid = threadIdx.x;
    for (int j = tid; j < 1280; j += 256) {
        int cc = j % 256;
        int k = j / 256;
        ws[cc * 5 + k] = w[k * 256 + cc];
    }
    __syncthreads();
    const int p = blockIdx.x * 256 + tid;
    const int n = p / HW;
    const int hw = p % HW;
    const float* xb = x + ((size_t)n * CH) * HW + hw;
    float a0 = 0.f, a1 = 0.f, a2 = 0.f, a3 = 0.f, a4 = 0.f;
#pragma unroll 4
    for (int c = 0; c < CH; ++c) {
        float xv = xb[c * HW];
        const float* wr = &ws[c * 5];
        a0 = fmaf(xv, wr[0], a0);
        a1 = fmaf(xv, wr[1], a1);
        a2 = fmaf(xv, wr[2], a2);
        a3 = fmaf(xv, wr[3], a3);
        a4 = fmaf(xv, wr[4], a4);
    }
    out_ctr[(size_t)n * HW + hw] = a0 + b[0];
    out_reg[((size_t)n * 4 + 0) * HW + hw] = fmaxf((a1 + b[1]) * sc, 0.f);
    out_reg[((size_t)n * 4 + 1) * HW + hw] = fmaxf((a2 + b[2]) * sc, 0.f);
    out_reg[((size_t)n * 4 + 2) * HW + hw] = fmaxf((a3 + b[3]) * sc, 0.f);
    out_reg[((size_t)n * 4 + 3) * HW + hw] = fmaxf((a4 + b[4]) * sc, 0.f);
}

// ---------------------------------------------------------------------------
// Host launcher (graph-capturable: kernel launches only).
// ---------------------------------------------------------------------------
extern "C" void kernel_launch(void* const* d_in, const int* in_sizes, int n_in,
                              void* d_out, int out_size) {
    const float* fpn[5];
    for (int i = 0; i < 5; ++i) fpn[i] = (const float*)d_in[i];
    const float* cls_conv_w   = (const float*)d_in[5];
    const float* cls_bn_scale = (const float*)d_in[6];
    const float* cls_bn_bias  = (const float*)d_in[7];
    const float* cls_final_w  = (const float*)d_in[8];
    const float* cls_final_b  = (const float*)d_in[9];
    const float* reg_conv_w   = (const float*)d_in[10];
    const float* reg_bn_scale = (const float*)d_in[11];
    const float* reg_bn_bias  = (const float*)d_in[12];
    const float* reg_final_w  = (const float*)d_in[13];
    const float* reg_final_b  = (const float*)d_in[14];
    float* out = (float*)d_out;

    float *bufA, *bufB, *wt;
    bf16 *xh, *xl, *yh, *yl;
    cudaGetSymbolAddress((void**)&bufA, g_bufA);
    cudaGetSymbolAddress((void**)&bufB, g_bufB);
    cudaGetSymbolAddress((void**)&wt,   g_wt);
    cudaGetSymbolAddress((void**)&xh, g_xh);
    cudaGetSymbolAddress((void**)&xl, g_xl);
    cudaGetSymbolAddress((void**)&yh, g_yh);
    cudaGetSymbolAddress((void**)&yl, g_yl);

    cudaFuncSetAttribute(conv3_tc<128, 128>,
                         cudaFuncAttributeMaxDynamicSharedMemorySize, TC_SMEM);
    cudaFuncSetAttribute(conv3_tc<64, 64>,
                         cudaFuncAttributeMaxDynamicSharedMemorySize, TC_SMEM);

    fold_weights_kernel<<<18432, 256>>>(cls_conv_w, cls_bn_scale, reg_conv_w, reg_bn_scale);
    fold_weights_bf16<<<18432, 256>>>(cls_conv_w, cls_bn_scale, reg_conv_w, reg_bn_scale);

    const int   Hs[5]  = {128, 64, 32, 16, 8};
    const float scs[5] = {8.f, 16.f, 32.f, 64.f, 128.f};
    size_t cls_off[5], reg_off[5], ctr_off[5];
    size_t a = 0;
    for (int l = 0; l < 5; ++l) { cls_off[l] = a; a += (size_t)4 * 80 * Hs[l] * Hs[l]; }
    for (int l = 0; l < 5; ++l) { reg_off[l] = a; a += (size_t)4 * 4  * Hs[l] * Hs[l]; }
    for (int l = 0; l < 5; ++l) { ctr_off[l] = a; a += (size_t)4 * 1  * Hs[l] * Hs[l]; }

    // zero padded activation buffers (level-0 footprint)
    {
        int n0 = PAD0 * 2 / 16;            // uint4 count
        int g0 = (n0 + 255) / 256;
        zero_k<<<g0, 256>>>((uint4*)xh, n0);
        zero_k<<<g0, 256>>>((uint4*)xl, n0);
        zero_k<<<g0, 256>>>((uint4*)yh, n0);
        zero_k<<<g0, 256>>>((uint4*)yl, n0);
    }

    // ---- levels 0,1: tcgen05 path ----
    for (int l = 0; l < 2; ++l) {
        const int H = Hs[l], W = Hs[l], HW = H * W;
        if (l == 1) {                       // re-zero level-1 footprint (layout change)
            int n1 = 4 * 66 * 66 * 256 * 2 / 16;
            int g1 = (n1 + 255) / 256;
            zero_k<<<g1, 256>>>((uint4*)xh, n1);
            zero_k<<<g1, 256>>>((uint4*)xl, n1);
            zero_k<<<g1, 256>>>((uint4*)yh, n1);
            zero_k<<<g1, 256>>>((uint4*)yl, n1);
        }
        for (int head = 0; head < 2; ++head) {
            const float* bnb = head ? reg_bn_bias : cls_bn_bias;
            dim3 tg(W / 32, H, 16);
            int tiles = 4 * HW / 128;
            if (l == 0) {
                transpose_in<128, 128><<<tg, 256>>>(fpn[l], xh, xl);
                conv3_tc<128, 128><<<tiles, 256, TC_SMEM>>>(xh, xl, yh, yl, bufB, 0, head * 4 + 0, bnb + 0);
                conv3_tc<128, 128><<<tiles, 256, TC_SMEM>>>(yh, yl, xh, xl, bufB, 0, head * 4 + 1, bnb + 256);
                conv3_tc<128, 128><<<tiles, 256, TC_SMEM>>>(xh, xl, yh, yl, bufB, 0, head * 4 + 2, bnb + 512);
                conv3_tc<128, 128><<<tiles, 256, TC_SMEM>>>(yh, yl, xh, xl, bufB, 1, head * 4 + 3, bnb + 768);
            } else {
                transpose_in<64, 64><<<tg, 256>>>(fpn[l], xh, xl);
                conv3_tc<64, 64><<<tiles, 256, TC_SMEM>>>(xh, xl, yh, yl, bufB, 0, head * 4 + 0, bnb + 0);
                conv3_tc<64, 64><<<tiles, 256, TC_SMEM>>>(yh, yl, xh, xl, bufB, 0, head * 4 + 1, bnb + 256);
                conv3_tc<64, 64><<<tiles, 256, TC_SMEM>>>(xh, xl, yh, yl, bufB, 0, head * 4 + 2, bnb + 512);
                conv3_tc<64, 64><<<tiles, 256, TC_SMEM>>>(yh, yl, xh, xl, bufB, 1, head * 4 + 3, bnb + 768);
            }
            const int PB = (4 * HW) / 256;
            if (head == 0)
                final_cls_kernel<<<PB, 256>>>(bufB, cls_final_w, cls_final_b,
                                              out + cls_off[l], HW);
            else
                final_reg_kernel<<<PB, 256>>>(bufB, reg_final_w, reg_final_b,
                                              out + reg_off[l], out + ctr_off[l], HW, scs[l]);
        }
    }

    // ---- levels 2..4: SIMT path ----
    for (int l = 2; l < 5; ++l) {
        const int H = Hs[l], W = Hs[l], HW = H * W;
        for (int head = 0; head < 2; ++head) {
            const float* bias_base = head ? reg_bn_bias : cls_bn_bias;
            float* bufs[2] = {bufA, bufB};
            for (int L = 0; L < 4; ++L) {
                const float* src = (L == 0) ? fpn[l] : bufs[(L + 1) & 1];
                float*       dst = bufs[L & 1];
                const float* wL  = wt + (size_t)(head * 4 + L) * 2304 * 256;
                dim3 grid(W / 8, H / 8, 16);
                conv3x3_small<<<grid, 256>>>(src, dst, wL, bias_base + L * 256, H, W);
            }
            const int PB = (4 * HW) / 256;
            if (head == 0)
                final_cls_kernel<<<PB, 256>>>(bufB, cls_final_w, cls_final_b,
                                              out + cls_off[l], HW);
            else
                final_reg_kernel<<<PB, 256>>>(bufB, reg_final_w, reg_final_b,
                                              out + reg_off[l], out + ctr_off[l], HW, scs[l]);
        }
    }
}